// round 2
// baseline (speedup 1.0000x reference)
#include <cuda_runtime.h>
#include <cstdint>
#include <cstddef>

// ---------------- problem constants ----------------
constexpr int Bn  = 4;      // batch
constexpr int Lq  = 1024;   // sequence length
constexpr int Dm  = 1024;   // d_model
constexpr int NH  = 16;     // heads
constexpr int HD  = 64;     // head dim
constexpr int NRr = 16;     // relations
constexpr int BL  = Bn * Lq; // 4096

// ---------------- device scratch (allocation-free rule: __device__ globals) ----
__device__ float g_q  [(size_t)BL * Dm];
__device__ float g_k  [(size_t)BL * Dm];
__device__ float g_qr [(size_t)BL * Dm];
__device__ float g_kr [(size_t)BL * Dm];
__device__ float g_sv [(size_t)BL * Dm];
__device__ float g_att[(size_t)BL * Dm];
__device__ float g_rel[(size_t)Bn * NRr * Lq * Lq];     // relations in [b,r,i,j] layout

// selectors for scratch buffers (kernels resolve device symbols directly; no
// cudaGetSymbolAddress on the host side, so kernel_launch is launches-only)
__device__ __forceinline__ float* scratch_ptr(int sel) {
    switch (sel) {
        case 0: return g_q;
        case 1: return g_k;
        case 2: return g_qr;
        case 3: return g_kr;
        case 4: return g_sv;
        case 5: return g_att;
        default: return g_rel;
    }
}

// =====================================================================
// gemm128_nn: C[M,N] = A[M,K] @ B[K,N], all row-major, M%128==0, N%128==0, K%8==0
// 128x128 tile, BK=8, 256 threads, 8x8 microtile.
// A source: external pointer if aSel<0 else scratch; C dest similar.
// =====================================================================
__global__ void gemm128_nn(const float* __restrict__ Aext, int aSel,
                           const float* __restrict__ Bm,
                           float* __restrict__ Cext, int cSel,
                           int M, int N, int K) {
    const float* A = (aSel < 0) ? Aext : scratch_ptr(aSel);
    float* C = (cSel < 0) ? Cext : scratch_ptr(cSel);

    __shared__ float As[8][128];
    __shared__ float Bs[8][128];
    const int tid = threadIdx.x;
    const int tx = tid & 15, ty = tid >> 4;
    const int row0 = blockIdx.y * 128, col0 = blockIdx.x * 128;
    const float* a = A + (size_t)row0 * K;
    const float* b = Bm + col0;
    float acc[8][8];
#pragma unroll
    for (int i = 0; i < 8; i++)
#pragma unroll
        for (int j = 0; j < 8; j++) acc[i][j] = 0.f;

    const int arow = tid >> 1, aseg = (tid & 1) * 4;
    const int brow = tid >> 5, bcol = (tid & 31) * 4;

    for (int k0 = 0; k0 < K; k0 += 8) {
        float4 av = *(const float4*)(a + (size_t)arow * K + k0 + aseg);
        As[aseg + 0][arow] = av.x;
        As[aseg + 1][arow] = av.y;
        As[aseg + 2][arow] = av.z;
        As[aseg + 3][arow] = av.w;
        *(float4*)&Bs[brow][bcol] = *(const float4*)(b + (size_t)(k0 + brow) * N + bcol);
        __syncthreads();
#pragma unroll
        for (int k = 0; k < 8; ++k) {
            float ra[8], rb[8];
            *(float4*)&ra[0] = *(const float4*)&As[k][ty * 8];
            *(float4*)&ra[4] = *(const float4*)&As[k][ty * 8 + 4];
            *(float4*)&rb[0] = *(const float4*)&Bs[k][tx * 8];
            *(float4*)&rb[4] = *(const float4*)&Bs[k][tx * 8 + 4];
#pragma unroll
            for (int i = 0; i < 8; i++)
#pragma unroll
                for (int j = 0; j < 8; j++) acc[i][j] += ra[i] * rb[j];
        }
        __syncthreads();
    }
#pragma unroll
    for (int i = 0; i < 8; i++) {
        float* cr = C + (size_t)(row0 + ty * 8 + i) * N + col0 + tx * 8;
        *(float4*)cr       = make_float4(acc[i][0], acc[i][1], acc[i][2], acc[i][3]);
        *(float4*)(cr + 4) = make_float4(acc[i][4], acc[i][5], acc[i][6], acc[i][7]);
    }
}

// =====================================================================
// gemm_nt128_b: batched over z in [0,64): b=z>>4, s=z&15
//   C_z[i,j] = scale * sum_{d<64} A[b,i,s,d] * B[b,j,s,d]
// qSel/kSel select scratch inputs; C dest = d_out region (ptr) or scratch sel.
// =====================================================================
__global__ void gemm_nt128_b(int qSel, int kSel,
                             float* __restrict__ Cext, int cSel, float scale) {
    const float* Qb = scratch_ptr(qSel);
    const float* Kb = scratch_ptr(kSel);
    float* Cb = (cSel < 0) ? Cext : scratch_ptr(cSel);

    __shared__ float As[8][128];
    __shared__ float Bs[8][128];
    const int tid = threadIdx.x;
    const int tx = tid & 15, ty = tid >> 4;
    const int z = blockIdx.z;
    const int bb = z >> 4, s = z & 15;
    const float* a = Qb + (size_t)bb * Lq * Dm + s * HD + (size_t)blockIdx.y * 128 * Dm;
    const float* b = Kb + (size_t)bb * Lq * Dm + s * HD + (size_t)blockIdx.x * 128 * Dm;
    float* c = Cb + (size_t)z * Lq * Lq + (size_t)blockIdx.y * 128 * Lq + blockIdx.x * 128;

    float acc[8][8];
#pragma unroll
    for (int i = 0; i < 8; i++)
#pragma unroll
        for (int j = 0; j < 8; j++) acc[i][j] = 0.f;

    const int lrow = tid >> 1, lseg = (tid & 1) * 4;

    for (int k0 = 0; k0 < HD; k0 += 8) {
        float4 av = *(const float4*)(a + (size_t)lrow * Dm + k0 + lseg);
        As[lseg + 0][lrow] = av.x;
        As[lseg + 1][lrow] = av.y;
        As[lseg + 2][lrow] = av.z;
        As[lseg + 3][lrow] = av.w;
        float4 bv = *(const float4*)(b + (size_t)lrow * Dm + k0 + lseg);
        Bs[lseg + 0][lrow] = bv.x;
        Bs[lseg + 1][lrow] = bv.y;
        Bs[lseg + 2][lrow] = bv.z;
        Bs[lseg + 3][lrow] = bv.w;
        __syncthreads();
#pragma unroll
        for (int k = 0; k < 8; ++k) {
            float ra[8], rb[8];
            *(float4*)&ra[0] = *(const float4*)&As[k][ty * 8];
            *(float4*)&ra[4] = *(const float4*)&As[k][ty * 8 + 4];
            *(float4*)&rb[0] = *(const float4*)&Bs[k][tx * 8];
            *(float4*)&rb[4] = *(const float4*)&Bs[k][tx * 8 + 4];
#pragma unroll
            for (int i = 0; i < 8; i++)
#pragma unroll
                for (int j = 0; j < 8; j++) acc[i][j] += ra[i] * rb[j];
        }
        __syncthreads();
    }
#pragma unroll
    for (int i = 0; i < 8; i++) {
        float* cr = c + (size_t)(ty * 8 + i) * Lq + tx * 8;
        *(float4*)cr = make_float4(acc[i][0] * scale, acc[i][1] * scale,
                                   acc[i][2] * scale, acc[i][3] * scale);
        *(float4*)(cr + 4) = make_float4(acc[i][4] * scale, acc[i][5] * scale,
                                         acc[i][6] * scale, acc[i][7] * scale);
    }
}

// =====================================================================
// softmax1024: in-place row softmax (rows of length 1024), one block per row.
// =====================================================================
__global__ void softmax1024(float* __restrict__ P) {
    float* p = P + (size_t)blockIdx.x * 1024;
    const int tid = threadIdx.x;
    const int wid = tid >> 5, lane = tid & 31;
    __shared__ float sred[8];

    float4 v = ((float4*)p)[tid];
    float m = fmaxf(fmaxf(v.x, v.y), fmaxf(v.z, v.w));
#pragma unroll
    for (int o = 16; o > 0; o >>= 1) m = fmaxf(m, __shfl_xor_sync(0xffffffffu, m, o));
    if (lane == 0) sred[wid] = m;
    __syncthreads();
    if (tid == 0) {
        float t = sred[0];
#pragma unroll
        for (int i = 1; i < 8; i++) t = fmaxf(t, sred[i]);
        sred[0] = t;
    }
    __syncthreads();
    const float rowmax = sred[0];
    __syncthreads();

    v.x = __expf(v.x - rowmax);
    v.y = __expf(v.y - rowmax);
    v.z = __expf(v.z - rowmax);
    v.w = __expf(v.w - rowmax);
    float ssum = v.x + v.y + v.z + v.w;
#pragma unroll
    for (int o = 16; o > 0; o >>= 1) ssum += __shfl_xor_sync(0xffffffffu, ssum, o);
    if (lane == 0) sred[wid] = ssum;
    __syncthreads();
    if (tid == 0) {
        float t = 0.f;
#pragma unroll
        for (int i = 0; i < 8; i++) t += sred[i];
        sred[0] = t;
    }
    __syncthreads();
    const float inv = 1.0f / sred[0];
    v.x *= inv; v.y *= inv; v.z *= inv; v.w *= inv;
    ((float4*)p)[tid] = v;
}

// =====================================================================
// rel_transpose: g_rel[b,r,i,j] -> relations[b,i,j,r]  (coalesced both sides via smem)
// grid (L/64, L, B), 256 threads.
// =====================================================================
__global__ void rel_transpose(float* __restrict__ RelOut) {
    const float* RelS = g_rel;
    const int j0 = blockIdx.x * 64;
    const int ii = blockIdx.y;
    const int bb = blockIdx.z;
    __shared__ float s[64][17];
    const int tid = threadIdx.x;
#pragma unroll
    for (int it = 0; it < 4; ++it) {
        int idx = it * 256 + tid;
        int r = idx >> 6, j = idx & 63;
        s[j][r] = RelS[(((size_t)bb * NRr + r) * Lq + ii) * Lq + j0 + j];
    }
    __syncthreads();
    const size_t base = (((size_t)bb * Lq + ii) * Lq + j0) * NRr;
#pragma unroll
    for (int it = 0; it < 4; ++it) {
        int idx = it * 256 + tid;
        RelOut[base + idx] = s[idx >> 4][idx & 15];
    }
}

// =====================================================================
// gemm_nn64_b (attended_symbols): per z=(b,h):
//   C[i,d] = sum_j attn[b,h,i,j] * sv[b,j,h,d]   (M=L, N=64, K=L)
// grid (L/64, 64), 256 threads, 4x4 microtile. Writes g_att with '='.
// =====================================================================
__global__ void gemm_nn64_b(const float* __restrict__ Attn) {
    const float* SV = g_sv;
    float* Catt = g_att;
    const int z = blockIdx.y;
    const int bb = z >> 4, h = z & 15;
    const float* a = Attn + (size_t)z * Lq * Lq + (size_t)blockIdx.x * 64 * Lq;
    const float* b = SV + (size_t)bb * Lq * Dm + h * HD;
    float* c = Catt + (size_t)bb * Lq * Dm + h * HD + (size_t)blockIdx.x * 64 * Dm;

    __shared__ float As[64][17];
    __shared__ float Bs[16][64];
    const int tid = threadIdx.x;
    const int tx = tid & 15, ty = tid >> 4;
    float acc[4][4];
#pragma unroll
    for (int i = 0; i < 4; i++)
#pragma unroll
        for (int j = 0; j < 4; j++) acc[i][j] = 0.f;

    const int arow = tid >> 2, aseg = (tid & 3) * 4;
    const int brow = tid >> 4, bcol = (tid & 15) * 4;

    for (int k0 = 0; k0 < Lq; k0 += 16) {
        float4 av = *(const float4*)(a + (size_t)arow * Lq + k0 + aseg);
        As[arow][aseg + 0] = av.x;
        As[arow][aseg + 1] = av.y;
        As[arow][aseg + 2] = av.z;
        As[arow][aseg + 3] = av.w;
        *(float4*)&Bs[brow][bcol] = *(const float4*)(b + (size_t)(k0 + brow) * Dm + bcol);
        __syncthreads();
#pragma unroll
        for (int k = 0; k < 16; ++k) {
            float rb[4];
            *(float4*)rb = *(const float4*)&Bs[k][tx * 4];
#pragma unroll
            for (int i = 0; i < 4; i++) {
                float ra = As[ty * 4 + i][k];
                acc[i][0] += ra * rb[0];
                acc[i][1] += ra * rb[1];
                acc[i][2] += ra * rb[2];
                acc[i][3] += ra * rb[3];
            }
        }
        __syncthreads();
    }
#pragma unroll
    for (int i = 0; i < 4; i++)
        *(float4*)(c + (size_t)(ty * 4 + i) * Dm + tx * 4) =
            make_float4(acc[i][0], acc[i][1], acc[i][2], acc[i][3]);
}

// =====================================================================
// t_ar_kernel: per (b,i):
//   t[h,r] = sum_j attn[b,h,i,j] * g_rel[b,r,i,j]
//   g_att[b,i,h*64+d] += sum_r t[h,r] * wr[h,d,r]
// grid B*L blocks, 256 threads (tid = h*16 + r).
// =====================================================================
__global__ void t_ar_kernel(const float* __restrict__ Attn, const float* __restrict__ Wr) {
    const float* RelS = g_rel;
    float* Catt = g_att;
    const int bi = blockIdx.x;
    const int bb = bi >> 10, ii = bi & 1023;
    const int tid = threadIdx.x;
    const int h = tid >> 4, r = tid & 15;
    __shared__ float a_s[16][260];
    __shared__ float r_s[16][260];
    __shared__ float t_s[16][17];
    float acc = 0.f;

    for (int jc = 0; jc < Lq; jc += 256) {
#pragma unroll
        for (int it = 0; it < 16; ++it) {
            a_s[it][tid] = Attn[(((size_t)bb * NH + it) * Lq + ii) * Lq + jc + tid];
            r_s[it][tid] = RelS[(((size_t)bb * NRr + it) * Lq + ii) * Lq + jc + tid];
        }
        __syncthreads();
#pragma unroll 8
        for (int c = 0; c < 256; c += 4) {
            float4 av = *(const float4*)&a_s[h][c];
            float4 rv = *(const float4*)&r_s[r][c];
            acc += av.x * rv.x + av.y * rv.y + av.z * rv.z + av.w * rv.w;
        }
        __syncthreads();
    }
    t_s[h][r] = acc;
    __syncthreads();

#pragma unroll
    for (int rep = 0; rep < 4; ++rep) {
        int idx = rep * 256 + tid;
        int h2 = idx >> 6, d = idx & 63;
        float v = 0.f;
#pragma unroll
        for (int rr = 0; rr < 16; ++rr) v += t_s[h2][rr] * Wr[(h2 * 64 + d) * 16 + rr];
        Catt[((size_t)bb * Lq + ii) * Dm + idx] += v;
    }
}

// =====================================================================
// launch — kernel launches ONLY (no runtime API calls at all)
// =====================================================================
extern "C" void kernel_launch(void* const* d_in, const int* in_sizes, int n_in,
                              void* d_out, int out_size) {
    (void)in_sizes; (void)n_in; (void)out_size;
    const float* x       = (const float*)d_in[0];
    const float* symbols = (const float*)d_in[1];
    const float* Wq_attn = (const float*)d_in[2];
    const float* Wk_attn = (const float*)d_in[3];
    const float* Wq_rel  = (const float*)d_in[4];
    const float* Wk_rel  = (const float*)d_in[5];
    const float* wr      = (const float*)d_in[6];
    const float* Wv      = (const float*)d_in[7];
    const float* Wo      = (const float*)d_in[8];
    float* out = (float*)d_out;

    const size_t OUT_E  = (size_t)BL * Dm;            // 4,194,304
    const size_t ATTN_E = (size_t)Bn * NH * Lq * Lq;  // 67,108,864
    float* attn = out + OUT_E;                        // [b, nh, L, L] region of d_out
    float* rel  = out + OUT_E + ATTN_E;               // [b, L, L, nr] region of d_out

    dim3 gproj(Dm / 128, BL / 128);  // (8, 32)

    // 1) projections into scratch (sel: 0=q 1=k 2=qr 3=kr 4=sv 5=att)
    gemm128_nn<<<gproj, 256>>>(x, -1, Wq_attn, nullptr, 0, BL, Dm, Dm);
    gemm128_nn<<<gproj, 256>>>(x, -1, Wk_attn, nullptr, 1, BL, Dm, Dm);
    gemm128_nn<<<gproj, 256>>>(x, -1, Wq_rel,  nullptr, 2, BL, Dm, Dm);
    gemm128_nn<<<gproj, 256>>>(x, -1, Wk_rel,  nullptr, 3, BL, Dm, Dm);
    gemm128_nn<<<gproj, 256>>>(symbols, -1, Wv, nullptr, 4, BL, Dm, Dm);

    // 2) attention scores -> attn region of d_out, softmax in-place
    gemm_nt128_b<<<dim3(8, 8, 64), 256>>>(0, 1, attn, -1, 0.125f);
    softmax1024<<<Bn * NH * Lq, 256>>>(attn);

    // 3) relations into [b,r,i,j] scratch (sel 6), then transpose to d_out layout
    gemm_nt128_b<<<dim3(8, 8, 64), 256>>>(2, 3, nullptr, 6, 0.125f);
    rel_transpose<<<dim3(Lq / 64, Lq, Bn), 256>>>(rel);

    // 4) attended_symbols -> g_att (writes), then t + attended_relations (adds)
    gemm_nn64_b<<<dim3(Lq / 64, 64), 256>>>(attn);
    t_ar_kernel<<<Bn * Lq, 256>>>(attn, wr);

    // 5) output projection: out = g_att @ Wo
    gemm128_nn<<<gproj, 256>>>(nullptr, 5, Wo, out, -1, BL, Dm, Dm);
}

// round 3
// speedup vs baseline: 1.5208x; 1.5208x over previous
#include <cuda_runtime.h>
#include <cstdint>
#include <cstddef>

// ---------------- problem constants ----------------
constexpr int Bn  = 4;      // batch
constexpr int Lq  = 1024;   // sequence length
constexpr int Dm  = 1024;   // d_model
constexpr int NH  = 16;     // heads
constexpr int HD  = 64;     // head dim
constexpr int NRr = 16;     // relations
constexpr int BL  = Bn * Lq; // 4096

// ---------------- device scratch (allocation-free rule: __device__ globals) ----
__device__ float g_q  [(size_t)BL * Dm];
__device__ float g_k  [(size_t)BL * Dm];
__device__ float g_qr [(size_t)BL * Dm];
__device__ float g_kr [(size_t)BL * Dm];
__device__ float g_sv [(size_t)BL * Dm];
__device__ float g_att[(size_t)BL * Dm];
__device__ float g_rel[(size_t)Bn * NRr * Lq * Lq];     // relations in [b,r,i,j] layout

__device__ __forceinline__ float* scratch_ptr(int sel) {
    switch (sel) {
        case 0: return g_q;
        case 1: return g_k;
        case 2: return g_qr;
        case 3: return g_kr;
        case 4: return g_sv;
        case 5: return g_att;
        default: return g_rel;
    }
}

// ---------------- tf32 helpers ----------------
__device__ __forceinline__ uint32_t f2tf32(float f) {
    uint32_t u;
    asm volatile("cvt.rna.tf32.f32 %0, %1;" : "=r"(u) : "f"(f));
    return u;
}

// D += A(16x8,row) * B(8x8,col); tf32 inputs, fp32 accum.
__device__ __forceinline__ void mma8(float* c, const uint32_t* a, const uint32_t* b) {
    asm volatile(
        "mma.sync.aligned.m16n8k8.row.col.f32.tf32.tf32.f32 "
        "{%0,%1,%2,%3}, {%4,%5,%6,%7}, {%8,%9}, {%0,%1,%2,%3};"
        : "+f"(c[0]), "+f"(c[1]), "+f"(c[2]), "+f"(c[3])
        : "r"(a[0]), "r"(a[1]), "r"(a[2]), "r"(a[3]), "r"(b[0]), "r"(b[1]));
}

constexpr int KS = 20;  // smem k-stride (16 + 4 pad) -> conflict-free frag LDS

// =====================================================================
// gemm_tc_nn128: C[M,N] = A[M,K] @ B[K,N] row-major, tf32 tensor cores.
// Block 128x128xBK16, 256 threads, warp grid 4(m) x 2(n), warp tile 32x64.
// Smem layout: As[m][k] and Bs[n][k], k-stride KS=20.
// =====================================================================
__global__ __launch_bounds__(256) void gemm_tc_nn128(
    const float* __restrict__ Aext, int aSel, const float* __restrict__ B,
    float* __restrict__ Cext, int cSel, int N, int K)
{
    const float* A = (aSel < 0) ? Aext : scratch_ptr(aSel);
    float* C = (cSel < 0) ? Cext : scratch_ptr(cSel);

    __shared__ uint32_t As[2][128 * KS];
    __shared__ uint32_t Bs[2][128 * KS];
    const int tid = threadIdx.x, lane = tid & 31, wid = tid >> 5;
    const int g = lane >> 2, t = lane & 3;
    const int wm = wid & 3, wn = wid >> 2;
    const int row0 = blockIdx.y * 128, col0 = blockIdx.x * 128;

    const int am = tid >> 2, ak4 = (tid & 3) * 4;   // A rows am, am+64; k seg ak4
    const int bk = tid >> 5, bn4 = (tid & 31) * 4;  // B k rows bk, bk+8; n seg bn4

    float acc[2][8][4];
#pragma unroll
    for (int i = 0; i < 2; i++)
#pragma unroll
        for (int j = 0; j < 8; j++)
#pragma unroll
            for (int q = 0; q < 4; q++) acc[i][j][q] = 0.f;

    float4 ra0, ra1, rb0, rb1;

    const int NTILES = K / 16;

    // prologue: tile 0
    {
        ra0 = *(const float4*)(A + (size_t)(row0 + am) * K + ak4);
        ra1 = *(const float4*)(A + (size_t)(row0 + am + 64) * K + ak4);
        rb0 = *(const float4*)(B + (size_t)bk * N + col0 + bn4);
        rb1 = *(const float4*)(B + (size_t)(bk + 8) * N + col0 + bn4);
        uint32_t* pa = &As[0][am * KS + ak4];
        pa[0] = f2tf32(ra0.x); pa[1] = f2tf32(ra0.y); pa[2] = f2tf32(ra0.z); pa[3] = f2tf32(ra0.w);
        pa = &As[0][(am + 64) * KS + ak4];
        pa[0] = f2tf32(ra1.x); pa[1] = f2tf32(ra1.y); pa[2] = f2tf32(ra1.z); pa[3] = f2tf32(ra1.w);
        Bs[0][(bn4 + 0) * KS + bk] = f2tf32(rb0.x);
        Bs[0][(bn4 + 1) * KS + bk] = f2tf32(rb0.y);
        Bs[0][(bn4 + 2) * KS + bk] = f2tf32(rb0.z);
        Bs[0][(bn4 + 3) * KS + bk] = f2tf32(rb0.w);
        Bs[0][(bn4 + 0) * KS + bk + 8] = f2tf32(rb1.x);
        Bs[0][(bn4 + 1) * KS + bk + 8] = f2tf32(rb1.y);
        Bs[0][(bn4 + 2) * KS + bk + 8] = f2tf32(rb1.z);
        Bs[0][(bn4 + 3) * KS + bk + 8] = f2tf32(rb1.w);
    }
    __syncthreads();

    for (int kt = 0; kt < NTILES; ++kt) {
        const int cur = kt & 1;
        if (kt + 1 < NTILES) {
            const int k0 = (kt + 1) * 16;
            ra0 = *(const float4*)(A + (size_t)(row0 + am) * K + k0 + ak4);
            ra1 = *(const float4*)(A + (size_t)(row0 + am + 64) * K + k0 + ak4);
            rb0 = *(const float4*)(B + (size_t)(k0 + bk) * N + col0 + bn4);
            rb1 = *(const float4*)(B + (size_t)(k0 + bk + 8) * N + col0 + bn4);
        }
#pragma unroll
        for (int k8 = 0; k8 < 2; ++k8) {
            const int kb = k8 * 8;
            uint32_t af[2][4];
#pragma unroll
            for (int mt = 0; mt < 2; ++mt) {
                const uint32_t* ap = &As[cur][(wm * 32 + mt * 16 + g) * KS + kb];
                af[mt][0] = ap[t];
                af[mt][1] = ap[8 * KS + t];
                af[mt][2] = ap[t + 4];
                af[mt][3] = ap[8 * KS + t + 4];
            }
#pragma unroll
            for (int nt = 0; nt < 8; ++nt) {
                const uint32_t* bp = &Bs[cur][(wn * 64 + nt * 8 + g) * KS + kb];
                uint32_t bf[2] = { bp[t], bp[t + 4] };
                mma8(acc[0][nt], af[0], bf);
                mma8(acc[1][nt], af[1], bf);
            }
        }
        if (kt + 1 < NTILES) {
            const int nxt = (kt + 1) & 1;
            uint32_t* pa = &As[nxt][am * KS + ak4];
            pa[0] = f2tf32(ra0.x); pa[1] = f2tf32(ra0.y); pa[2] = f2tf32(ra0.z); pa[3] = f2tf32(ra0.w);
            pa = &As[nxt][(am + 64) * KS + ak4];
            pa[0] = f2tf32(ra1.x); pa[1] = f2tf32(ra1.y); pa[2] = f2tf32(ra1.z); pa[3] = f2tf32(ra1.w);
            Bs[nxt][(bn4 + 0) * KS + bk] = f2tf32(rb0.x);
            Bs[nxt][(bn4 + 1) * KS + bk] = f2tf32(rb0.y);
            Bs[nxt][(bn4 + 2) * KS + bk] = f2tf32(rb0.z);
            Bs[nxt][(bn4 + 3) * KS + bk] = f2tf32(rb0.w);
            Bs[nxt][(bn4 + 0) * KS + bk + 8] = f2tf32(rb1.x);
            Bs[nxt][(bn4 + 1) * KS + bk + 8] = f2tf32(rb1.y);
            Bs[nxt][(bn4 + 2) * KS + bk + 8] = f2tf32(rb1.z);
            Bs[nxt][(bn4 + 3) * KS + bk + 8] = f2tf32(rb1.w);
            __syncthreads();
        }
    }

#pragma unroll
    for (int mt = 0; mt < 2; ++mt)
#pragma unroll
        for (int nt = 0; nt < 8; ++nt) {
            const int r = row0 + wm * 32 + mt * 16 + g;
            const int c = col0 + wn * 64 + nt * 8 + 2 * t;
            *(float2*)&C[(size_t)r * N + c]       = make_float2(acc[mt][nt][0], acc[mt][nt][1]);
            *(float2*)&C[(size_t)(r + 8) * N + c] = make_float2(acc[mt][nt][2], acc[mt][nt][3]);
        }
}

// =====================================================================
// gemm_tc_nt_b: batched z in [0,64): b=z>>4, s=z&15
//   C_z[i,j] = scale * sum_{d<64} Q[b,i,s,d] * Km[b,j,s,d]
// Both operands row-major with k(=d) contiguous. Same block/warp tiling.
// =====================================================================
__global__ __launch_bounds__(256) void gemm_tc_nt_b(
    int qSel, int kSel, float* __restrict__ Cext, int cSel, float scale)
{
    const float* Qb = scratch_ptr(qSel);
    const float* Kb = scratch_ptr(kSel);
    float* Cb = (cSel < 0) ? Cext : scratch_ptr(cSel);

    __shared__ uint32_t As[2][128 * KS];
    __shared__ uint32_t Bs[2][128 * KS];
    const int tid = threadIdx.x, lane = tid & 31, wid = tid >> 5;
    const int g = lane >> 2, t = lane & 3;
    const int wm = wid & 3, wn = wid >> 2;
    const int z = blockIdx.z, bb = z >> 4, s = z & 15;
    const int row0 = blockIdx.y * 128, col0 = blockIdx.x * 128;

    const float* A = Qb + (size_t)bb * Lq * Dm + s * HD;
    const float* B = Kb + (size_t)bb * Lq * Dm + s * HD;
    float* C = Cb + (size_t)z * Lq * Lq;

    const int am = tid >> 2, ak4 = (tid & 3) * 4;  // rows am, am+64 of each operand

    float acc[2][8][4];
#pragma unroll
    for (int i = 0; i < 2; i++)
#pragma unroll
        for (int j = 0; j < 8; j++)
#pragma unroll
            for (int q = 0; q < 4; q++) acc[i][j][q] = 0.f;

    float4 ra0, ra1, rb0, rb1;
    const int NTILES = HD / 16;  // 4

    {
        ra0 = *(const float4*)(A + (size_t)(row0 + am) * Dm + ak4);
        ra1 = *(const float4*)(A + (size_t)(row0 + am + 64) * Dm + ak4);
        rb0 = *(const float4*)(B + (size_t)(col0 + am) * Dm + ak4);
        rb1 = *(const float4*)(B + (size_t)(col0 + am + 64) * Dm + ak4);
        uint32_t* p = &As[0][am * KS + ak4];
        p[0] = f2tf32(ra0.x); p[1] = f2tf32(ra0.y); p[2] = f2tf32(ra0.z); p[3] = f2tf32(ra0.w);
        p = &As[0][(am + 64) * KS + ak4];
        p[0] = f2tf32(ra1.x); p[1] = f2tf32(ra1.y); p[2] = f2tf32(ra1.z); p[3] = f2tf32(ra1.w);
        p = &Bs[0][am * KS + ak4];
        p[0] = f2tf32(rb0.x); p[1] = f2tf32(rb0.y); p[2] = f2tf32(rb0.z); p[3] = f2tf32(rb0.w);
        p = &Bs[0][(am + 64) * KS + ak4];
        p[0] = f2tf32(rb1.x); p[1] = f2tf32(rb1.y); p[2] = f2tf32(rb1.z); p[3] = f2tf32(rb1.w);
    }
    __syncthreads();

    for (int kt = 0; kt < NTILES; ++kt) {
        const int cur = kt & 1;
        if (kt + 1 < NTILES) {
            const int k0 = (kt + 1) * 16;
            ra0 = *(const float4*)(A + (size_t)(row0 + am) * Dm + k0 + ak4);
            ra1 = *(const float4*)(A + (size_t)(row0 + am + 64) * Dm + k0 + ak4);
            rb0 = *(const float4*)(B + (size_t)(col0 + am) * Dm + k0 + ak4);
            rb1 = *(const float4*)(B + (size_t)(col0 + am + 64) * Dm + k0 + ak4);
        }
#pragma unroll
        for (int k8 = 0; k8 < 2; ++k8) {
            const int kb = k8 * 8;
            uint32_t af[2][4];
#pragma unroll
            for (int mt = 0; mt < 2; ++mt) {
                const uint32_t* ap = &As[cur][(wm * 32 + mt * 16 + g) * KS + kb];
                af[mt][0] = ap[t];
                af[mt][1] = ap[8 * KS + t];
                af[mt][2] = ap[t + 4];
                af[mt][3] = ap[8 * KS + t + 4];
            }
#pragma unroll
            for (int nt = 0; nt < 8; ++nt) {
                const uint32_t* bp = &Bs[cur][(wn * 64 + nt * 8 + g) * KS + kb];
                uint32_t bf[2] = { bp[t], bp[t + 4] };
                mma8(acc[0][nt], af[0], bf);
                mma8(acc[1][nt], af[1], bf);
            }
        }
        if (kt + 1 < NTILES) {
            const int nxt = (kt + 1) & 1;
            uint32_t* p = &As[nxt][am * KS + ak4];
            p[0] = f2tf32(ra0.x); p[1] = f2tf32(ra0.y); p[2] = f2tf32(ra0.z); p[3] = f2tf32(ra0.w);
            p = &As[nxt][(am + 64) * KS + ak4];
            p[0] = f2tf32(ra1.x); p[1] = f2tf32(ra1.y); p[2] = f2tf32(ra1.z); p[3] = f2tf32(ra1.w);
            p = &Bs[nxt][am * KS + ak4];
            p[0] = f2tf32(rb0.x); p[1] = f2tf32(rb0.y); p[2] = f2tf32(rb0.z); p[3] = f2tf32(rb0.w);
            p = &Bs[nxt][(am + 64) * KS + ak4];
            p[0] = f2tf32(rb1.x); p[1] = f2tf32(rb1.y); p[2] = f2tf32(rb1.z); p[3] = f2tf32(rb1.w);
            __syncthreads();
        }
    }

#pragma unroll
    for (int mt = 0; mt < 2; ++mt)
#pragma unroll
        for (int nt = 0; nt < 8; ++nt) {
            const int r = row0 + wm * 32 + mt * 16 + g;
            const int c = col0 + wn * 64 + nt * 8 + 2 * t;
            *(float2*)&C[(size_t)r * Lq + c] =
                make_float2(acc[mt][nt][0] * scale, acc[mt][nt][1] * scale);
            *(float2*)&C[(size_t)(r + 8) * Lq + c] =
                make_float2(acc[mt][nt][2] * scale, acc[mt][nt][3] * scale);
        }
}

// =====================================================================
// gemm_tc_av (attended_symbols): per z=(b,h):
//   C[i,d] = sum_j attn[b,h,i,j] * sv[b,j,h,d]   (M=L, N=64, K=L)
// Block 128x64, 256 threads, 8 warps along m, warp tile 16x64.
// =====================================================================
__global__ __launch_bounds__(256) void gemm_tc_av(const float* __restrict__ Attn)
{
    const float* SVb = g_sv;
    float* Catt = g_att;
    const int z = blockIdx.z, bb = z >> 4, h = z & 15;
    const int row0 = blockIdx.y * 128;

    const float* A = Attn + (size_t)z * Lq * Lq;
    const float* B = SVb + (size_t)bb * Lq * Dm + h * HD;
    float* C = Catt + (size_t)bb * Lq * Dm + h * HD;

    __shared__ uint32_t As[2][128 * KS];
    __shared__ uint32_t Bs[2][64 * KS];
    const int tid = threadIdx.x, lane = tid & 31, wid = tid >> 5;
    const int g = lane >> 2, t = lane & 3;

    const int am = tid >> 2, ak4 = (tid & 3) * 4;
    const int bkk = tid >> 4, bn4 = (tid & 15) * 4;

    float acc[8][4];
#pragma unroll
    for (int j = 0; j < 8; j++)
#pragma unroll
        for (int q = 0; q < 4; q++) acc[j][q] = 0.f;

    float4 ra0, ra1, rb;
    const int NTILES = Lq / 16;  // 64

    {
        ra0 = *(const float4*)(A + (size_t)(row0 + am) * Lq + ak4);
        ra1 = *(const float4*)(A + (size_t)(row0 + am + 64) * Lq + ak4);
        rb  = *(const float4*)(B + (size_t)bkk * Dm + bn4);
        uint32_t* p = &As[0][am * KS + ak4];
        p[0] = f2tf32(ra0.x); p[1] = f2tf32(ra0.y); p[2] = f2tf32(ra0.z); p[3] = f2tf32(ra0.w);
        p = &As[0][(am + 64) * KS + ak4];
        p[0] = f2tf32(ra1.x); p[1] = f2tf32(ra1.y); p[2] = f2tf32(ra1.z); p[3] = f2tf32(ra1.w);
        Bs[0][(bn4 + 0) * KS + bkk] = f2tf32(rb.x);
        Bs[0][(bn4 + 1) * KS + bkk] = f2tf32(rb.y);
        Bs[0][(bn4 + 2) * KS + bkk] = f2tf32(rb.z);
        Bs[0][(bn4 + 3) * KS + bkk] = f2tf32(rb.w);
    }
    __syncthreads();

    for (int kt = 0; kt < NTILES; ++kt) {
        const int cur = kt & 1;
        if (kt + 1 < NTILES) {
            const int k0 = (kt + 1) * 16;
            ra0 = *(const float4*)(A + (size_t)(row0 + am) * Lq + k0 + ak4);
            ra1 = *(const float4*)(A + (size_t)(row0 + am + 64) * Lq + k0 + ak4);
            rb  = *(const float4*)(B + (size_t)(k0 + bkk) * Dm + bn4);
        }
#pragma unroll
        for (int k8 = 0; k8 < 2; ++k8) {
            const int kb = k8 * 8;
            uint32_t af[4];
            {
                const uint32_t* ap = &As[cur][(wid * 16 + g) * KS + kb];
                af[0] = ap[t];
                af[1] = ap[8 * KS + t];
                af[2] = ap[t + 4];
                af[3] = ap[8 * KS + t + 4];
            }
#pragma unroll
            for (int nt = 0; nt < 8; ++nt) {
                const uint32_t* bp = &Bs[cur][(nt * 8 + g) * KS + kb];
                uint32_t bf[2] = { bp[t], bp[t + 4] };
                mma8(acc[nt], af, bf);
            }
        }
        if (kt + 1 < NTILES) {
            const int nxt = (kt + 1) & 1;
            uint32_t* p = &As[nxt][am * KS + ak4];
            p[0] = f2tf32(ra0.x); p[1] = f2tf32(ra0.y); p[2] = f2tf32(ra0.z); p[3] = f2tf32(ra0.w);
            p = &As[nxt][(am + 64) * KS + ak4];
            p[0] = f2tf32(ra1.x); p[1] = f2tf32(ra1.y); p[2] = f2tf32(ra1.z); p[3] = f2tf32(ra1.w);
            Bs[nxt][(bn4 + 0) * KS + bkk] = f2tf32(rb.x);
            Bs[nxt][(bn4 + 1) * KS + bkk] = f2tf32(rb.y);
            Bs[nxt][(bn4 + 2) * KS + bkk] = f2tf32(rb.z);
            Bs[nxt][(bn4 + 3) * KS + bkk] = f2tf32(rb.w);
            __syncthreads();
        }
    }

#pragma unroll
    for (int nt = 0; nt < 8; ++nt) {
        const int r = row0 + wid * 16 + g;
        const int c = nt * 8 + 2 * t;
        *(float2*)&C[(size_t)r * Dm + c]       = make_float2(acc[nt][0], acc[nt][1]);
        *(float2*)&C[(size_t)(r + 8) * Dm + c] = make_float2(acc[nt][2], acc[nt][3]);
    }
}

// =====================================================================
// softmax1024: in-place row softmax (rows of length 1024), one block per row.
// =====================================================================
__global__ void softmax1024(float* __restrict__ P) {
    float* p = P + (size_t)blockIdx.x * 1024;
    const int tid = threadIdx.x;
    const int wid = tid >> 5, lane = tid & 31;
    __shared__ float sred[8];

    float4 v = ((float4*)p)[tid];
    float m = fmaxf(fmaxf(v.x, v.y), fmaxf(v.z, v.w));
#pragma unroll
    for (int o = 16; o > 0; o >>= 1) m = fmaxf(m, __shfl_xor_sync(0xffffffffu, m, o));
    if (lane == 0) sred[wid] = m;
    __syncthreads();
    if (tid == 0) {
        float tt = sred[0];
#pragma unroll
        for (int i = 1; i < 8; i++) tt = fmaxf(tt, sred[i]);
        sred[0] = tt;
    }
    __syncthreads();
    const float rowmax = sred[0];
    __syncthreads();

    v.x = __expf(v.x - rowmax);
    v.y = __expf(v.y - rowmax);
    v.z = __expf(v.z - rowmax);
    v.w = __expf(v.w - rowmax);
    float ssum = v.x + v.y + v.z + v.w;
#pragma unroll
    for (int o = 16; o > 0; o >>= 1) ssum += __shfl_xor_sync(0xffffffffu, ssum, o);
    if (lane == 0) sred[wid] = ssum;
    __syncthreads();
    if (tid == 0) {
        float tt = 0.f;
#pragma unroll
        for (int i = 0; i < 8; i++) tt += sred[i];
        sred[0] = tt;
    }
    __syncthreads();
    const float inv = 1.0f / sred[0];
    v.x *= inv; v.y *= inv; v.z *= inv; v.w *= inv;
    ((float4*)p)[tid] = v;
}

// =====================================================================
// rel_transpose: g_rel[b,r,i,j] -> relations[b,i,j,r]
// =====================================================================
__global__ void rel_transpose(float* __restrict__ RelOut) {
    const float* RelS = g_rel;
    const int j0 = blockIdx.x * 64;
    const int ii = blockIdx.y;
    const int bb = blockIdx.z;
    __shared__ float s[64][17];
    const int tid = threadIdx.x;
#pragma unroll
    for (int it = 0; it < 4; ++it) {
        int idx = it * 256 + tid;
        int r = idx >> 6, j = idx & 63;
        s[j][r] = RelS[(((size_t)bb * NRr + r) * Lq + ii) * Lq + j0 + j];
    }
    __syncthreads();
    const size_t base = (((size_t)bb * Lq + ii) * Lq + j0) * NRr;
#pragma unroll
    for (int it = 0; it < 4; ++it) {
        int idx = it * 256 + tid;
        RelOut[base + idx] = s[idx >> 4][idx & 15];
    }
}

// =====================================================================
// t_ar_kernel: per (b,i):
//   t[h,r] = sum_j attn[b,h,i,j] * g_rel[b,r,i,j]
//   g_att[b,i,h*64+d] += sum_r t[h,r] * wr[h,d,r]
// =====================================================================
__global__ void t_ar_kernel(const float* __restrict__ Attn, const float* __restrict__ Wr) {
    const float* RelS = g_rel;
    float* Catt = g_att;
    const int bi = blockIdx.x;
    const int bb = bi >> 10, ii = bi & 1023;
    const int tid = threadIdx.x;
    const int h = tid >> 4, r = tid & 15;
    __shared__ float a_s[16][260];
    __shared__ float r_s[16][260];
    __shared__ float t_s[16][17];
    float acc = 0.f;

    for (int jc = 0; jc < Lq; jc += 256) {
#pragma unroll
        for (int it = 0; it < 16; ++it) {
            a_s[it][tid] = Attn[(((size_t)bb * NH + it) * Lq + ii) * Lq + jc + tid];
            r_s[it][tid] = RelS[(((size_t)bb * NRr + it) * Lq + ii) * Lq + jc + tid];
        }
        __syncthreads();
#pragma unroll 8
        for (int c = 0; c < 256; c += 4) {
            float4 av = *(const float4*)&a_s[h][c];
            float4 rv = *(const float4*)&r_s[r][c];
            acc += av.x * rv.x + av.y * rv.y + av.z * rv.z + av.w * rv.w;
        }
        __syncthreads();
    }
    t_s[h][r] = acc;
    __syncthreads();

#pragma unroll
    for (int rep = 0; rep < 4; ++rep) {
        int idx = rep * 256 + tid;
        int h2 = idx >> 6, d = idx & 63;
        float v = 0.f;
#pragma unroll
        for (int rr = 0; rr < 16; ++rr) v += t_s[h2][rr] * Wr[(h2 * 64 + d) * 16 + rr];
        Catt[((size_t)bb * Lq + ii) * Dm + idx] += v;
    }
}

// =====================================================================
// launch — kernel launches ONLY
// =====================================================================
extern "C" void kernel_launch(void* const* d_in, const int* in_sizes, int n_in,
                              void* d_out, int out_size) {
    (void)in_sizes; (void)n_in; (void)out_size;
    const float* x       = (const float*)d_in[0];
    const float* symbols = (const float*)d_in[1];
    const float* Wq_attn = (const float*)d_in[2];
    const float* Wk_attn = (const float*)d_in[3];
    const float* Wq_rel  = (const float*)d_in[4];
    const float* Wk_rel  = (const float*)d_in[5];
    const float* wr      = (const float*)d_in[6];
    const float* Wv      = (const float*)d_in[7];
    const float* Wo      = (const float*)d_in[8];
    float* out = (float*)d_out;

    const size_t OUT_E  = (size_t)BL * Dm;            // 4,194,304
    const size_t ATTN_E = (size_t)Bn * NH * Lq * Lq;  // 67,108,864
    float* attn = out + OUT_E;                        // [b, nh, L, L] region of d_out
    float* rel  = out + OUT_E + ATTN_E;               // [b, L, L, nr] region of d_out

    dim3 gproj(Dm / 128, BL / 128);  // (8, 32)

    // 1) projections into scratch (sel: 0=q 1=k 2=qr 3=kr 4=sv 5=att)
    gemm_tc_nn128<<<gproj, 256>>>(x, -1, Wq_attn, nullptr, 0, Dm, Dm);
    gemm_tc_nn128<<<gproj, 256>>>(x, -1, Wk_attn, nullptr, 1, Dm, Dm);
    gemm_tc_nn128<<<gproj, 256>>>(x, -1, Wq_rel,  nullptr, 2, Dm, Dm);
    gemm_tc_nn128<<<gproj, 256>>>(x, -1, Wk_rel,  nullptr, 3, Dm, Dm);
    gemm_tc_nn128<<<gproj, 256>>>(symbols, -1, Wv, nullptr, 4, Dm, Dm);

    // 2) attention scores -> attn region of d_out, softmax in-place
    gemm_tc_nt_b<<<dim3(8, 8, 64), 256>>>(0, 1, attn, -1, 0.125f);
    softmax1024<<<Bn * NH * Lq, 256>>>(attn);

    // 3) relations into [b,r,i,j] scratch (sel 6), then transpose to d_out layout
    gemm_tc_nt_b<<<dim3(8, 8, 64), 256>>>(2, 3, nullptr, 6, 0.125f);
    rel_transpose<<<dim3(Lq / 64, Lq, Bn), 256>>>(rel);

    // 4) attended_symbols -> g_att (writes), then t + attended_relations (adds)
    gemm_tc_av<<<dim3(1, 8, 64), 256>>>(attn);
    t_ar_kernel<<<Bn * Lq, 256>>>(attn, wr);

    // 5) output projection: out = g_att @ Wo
    gemm_tc_nn128<<<gproj, 256>>>(nullptr, 5, Wo, out, -1, Dm, Dm);
}